// round 13
// baseline (speedup 1.0000x reference)
#include <cuda_runtime.h>

#define BB 128
#define TT 256
#define DD 256
#define UU 256
#define ZZ 1024   // 4*U
#define NP 82
#define NSCAN 128
#define NTILES 8192   // per proj layer: 2 dir x 256 t x 8 nb x 2 mh

// ---------------- scratch (device globals; no allocation allowed) ----------------
__device__ float g_xz0[2][TT * BB * ZZ];      // layer-0 gate inputs [dir][t][b][u*4+g]
__device__ float g_xz1[2][TT * BB * ZZ];      // layer-1 gate inputs
__device__ float g_h0[2][TT * BB * UU];       // layer-0 outputs [dir][t][b][u]
__device__ float g_h1[2][TT * BB * UU];       // layer-1 raw lstm outputs
__device__ float g_hTL[2][2][2][UU * BB];     // [layer][buf][dir][u][b]
__device__ float g_Wp[2][2][DD * ZZ];         // [layer][dir][k][u*4+g]
__device__ float g_Rblk[2 * 2 * 16 * 256 * 64]; // [layer][dir][zi][k][64] per-CTA contiguous
__device__ float g_bp[2][2][ZZ];
__device__ int g_cnt0[8], g_gen0[8];          // scan0 barriers (dir x bq)
__device__ int g_cnt1[8], g_gen1[8];          // scan1 barriers
__device__ int g_pd0[2][TT];                  // proj0 tiles done per (dir,t), target 16
__device__ int g_pd1[2][TT];
__device__ int g_tk0, g_tk1;                  // proj tile tickets

// ---------------- packed f32x2 helpers ---------------------------------------------
__device__ __forceinline__ void fma2(unsigned long long& d, unsigned long long a,
                                     unsigned long long b) {
    asm("fma.rn.f32x2 %0, %1, %2, %0;" : "+l"(d) : "l"(a), "l"(b));
}
__device__ __forceinline__ unsigned long long pack2(float x) {
    unsigned long long d; unsigned int u = __float_as_uint(x);
    asm("mov.b64 %0, {%1, %1};" : "=l"(d) : "r"(u));
    return d;
}
__device__ __forceinline__ void unpack2(unsigned long long v, float& lo, float& hi) {
    unsigned int a, b;
    asm("mov.b64 {%0, %1}, %2;" : "=r"(a), "=r"(b) : "l"(v));
    lo = __uint_as_float(a); hi = __uint_as_float(b);
}

// ---------------- acquire/release primitives ----------------------------------------
__device__ __forceinline__ int atom_add_acqrel(int* p) {
    int old;
    asm volatile("atom.acq_rel.gpu.global.add.s32 %0, [%1], 1;"
                 : "=r"(old) : "l"(p) : "memory");
    return old;
}
__device__ __forceinline__ void st_release(int* p, int v) {
    asm volatile("st.release.gpu.global.s32 [%0], %1;" :: "l"(p), "r"(v) : "memory");
}
__device__ __forceinline__ int ld_acquire(int* p) {
    int v;
    asm volatile("ld.acquire.gpu.global.s32 %0, [%1];" : "=r"(v) : "l"(p) : "memory");
    return v;
}

// ---------------- cp.async helpers --------------------------------------------------
__device__ __forceinline__ void cpa16(void* smem, const void* g) {
    unsigned s = (unsigned)__cvta_generic_to_shared(smem);
    asm volatile("cp.async.cg.shared.global [%0], [%1], 16;" :: "r"(s), "l"(g));
}
__device__ __forceinline__ void cpa_commit() { asm volatile("cp.async.commit_group;"); }
__device__ __forceinline__ void cpa_wait0()  { asm volatile("cp.async.wait_group 0;"); }
__device__ __forceinline__ void cpa_wait1()  { asm volatile("cp.async.wait_group 1;"); }

// ---------------- MUFU-free fast math ----------------------------------------------
__device__ __forceinline__ float fast_exp(float x) {
    x = fminf(fmaxf(x, -80.0f), 80.0f);
    float y = x * 1.442695041f;
    float t = y + 12582912.0f;
    float n = t - 12582912.0f;
    float f = y - n;
    int   ni = __float_as_int(t) - 0x4B400000;
    float p = 1.54035304e-4f;
    p = fmaf(p, f, 1.33335581e-3f);
    p = fmaf(p, f, 9.61812910e-3f);
    p = fmaf(p, f, 5.55041087e-2f);
    p = fmaf(p, f, 2.40226507e-1f);
    p = fmaf(p, f, 6.93147182e-1f);
    p = fmaf(p, f, 1.0f);
    return p * __int_as_float((ni + 127) << 23);
}
__device__ __forceinline__ float fast_rcp(float a) {
    float r = __int_as_float(0x7EF311C3 - __float_as_int(a));
    r = r * fmaf(-a, r, 2.0f);
    r = r * fmaf(-a, r, 2.0f);
    r = r * fmaf(-a, r, 2.0f);
    return r;
}
__device__ __forceinline__ float sigm_(float x) { return fast_rcp(1.0f + fast_exp(-x)); }
__device__ __forceinline__ float tanh_(float x) { return fmaf(-2.0f, fast_rcp(1.0f + fast_exp(2.0f * x)), 1.0f); }

// ---------------- weight permutation -------------------------------------------------
__global__ void prep_kernel(const float* __restrict__ kfw, const float* __restrict__ rfw,
                            const float* __restrict__ bfw, const float* __restrict__ kbw,
                            const float* __restrict__ rbw, const float* __restrict__ bbw) {
    int idx = blockIdx.x * blockDim.x + threadIdx.x;
    if (idx >= 2 * 2 * DD * ZZ) return;
    int e  = idx & (DD * ZZ - 1);
    int ld = idx >> 18;
    int l = ld >> 1, d = ld & 1;
    int k  = e >> 10;
    int uu = e & 1023;
    int u = uu >> 2, g = uu & 3;
    int src_col = g * UU + u;
    const float* Ksrc = d ? kbw : kfw;
    const float* Rsrc = d ? rbw : rfw;
    g_Wp[l][d][e] = Ksrc[l * DD * ZZ + k * ZZ + src_col];
    int zi = u >> 4, zg = u & 15;
    g_Rblk[(((l * 2 + d) * 16 + zi) << 14) + k * 64 + zg * 4 + g] =
        Rsrc[l * UU * ZZ + k * ZZ + src_col];
    if (k == 0) {
        const float* bsrc = d ? bbw : bfw;
        g_bp[l][d][uu] = bsrc[l * ZZ + src_col];
    }
}

__global__ void zero_bar_kernel() {
    int i = threadIdx.x;
    if (i < 8) { g_cnt0[i] = 0; g_gen0[i] = 0; g_cnt1[i] = 0; g_gen1[i] = 0; }
    if (i < 512) { ((int*)g_pd0)[i] = 0; ((int*)g_pd1)[i] = 0; }
    if (i == 0) { g_tk0 = 0; g_tk1 = 0; }
}

// ---------------- scan body (per layer): 128 CTAs, groups of 16 ---------------------
// CTA = (dir, bq 32b, zi 16 units). Thread = 2 cells (2 batches x 1 unit), full k.
// R streamed from L2 in 4 x 16KB double-buffered chunks; h tile in smem.
__device__ __forceinline__ void scan_body(int layer, int sub, float* sm) {
    float* hs    = sm;                 // [256 k][32 b]  32 KB
    float* Rb    = sm + 8192;          // 2 x 4096       32 KB
    float* stage = sm + 16384;         // [32 b][16 u]    2 KB

    int dir = sub >> 6, rest = sub & 63;
    int bq = rest >> 4, zi = rest & 15;
    int b0 = bq * 32, u0 = zi * 16, zc0 = zi * 64;
    int grp = dir * 4 + bq;
    int tid = threadIdx.x;
    int zg = tid & 15, bp2 = tid >> 4;
    int brow = b0 + 2 * bp2;

    int* cnt = layer ? g_cnt1 : g_cnt0;
    int* gen = layer ? g_gen1 : g_gen0;
    int* pd  = layer ? g_pd1[dir] : g_pd0[dir];
    const float* xzb = (layer ? g_xz1 : g_xz0)[dir];
    float* outb = (layer ? g_h1 : g_h0)[dir];
    const float* Rglob = g_Rblk + (((layer * 2 + dir) * 16 + zi) << 14);

    float cc0 = 0.0f, cc1 = 0.0f;
    int t0 = dir ? (TT - 1) : 0;
    if (tid == 0) { while (ld_acquire(&pd[t0]) < 16) { } }
    __syncthreads();
    float4 xv0 = *(const float4*)(xzb + (size_t)(t0 * BB + brow) * ZZ + zc0 + zg * 4);
    float4 xv1 = *(const float4*)(xzb + (size_t)(t0 * BB + brow + 1) * ZZ + zc0 + zg * 4);

    for (int s = 0; s < TT; s++) {
        int t  = dir ? (TT - 1 - s) : s;
        int rd = s & 1, wr = rd ^ 1;
        unsigned long long a00 = 0, a01 = 0, a10 = 0, a11 = 0;

        if (s > 0) {
            // group0: h fill + R chunk0 ; group1: R chunk1
            const float* hsrc = g_hTL[layer][rd][dir] + b0;
#pragma unroll
            for (int r = 0; r < 8; r++) {
                int i = tid + r * 256;            // 0..2047 float4s
                int k = i >> 3, q = i & 7;
                cpa16(&hs[k * 32 + q * 4], hsrc + k * BB + q * 4);
            }
#pragma unroll
            for (int ii = 0; ii < 4; ii++)
                cpa16(&Rb[(tid + ii * 256) * 4], Rglob + (size_t)(tid + ii * 256) * 4);
            cpa_commit();   // g0
#pragma unroll
            for (int ii = 0; ii < 4; ii++)
                cpa16(&Rb[4096 + (tid + ii * 256) * 4],
                      Rglob + 4096 + (size_t)(tid + ii * 256) * 4);
            cpa_commit();   // g1
            cpa_wait1();    // g0 (h + R0) done
            __syncthreads();

            for (int c = 0; c < 4; c++) {
                const float* hb = hs + c * 64 * 32 + 2 * bp2;
                const float* rb = Rb + (c & 1) * 4096 + zg * 4;
#pragma unroll 4
                for (int k = 0; k < 64; k++) {
                    float2 hv = *(const float2*)(hb + k * 32);
                    ulonglong2 rv = *(const ulonglong2*)(rb + k * 64);
                    unsigned long long h0 = pack2(hv.x), h1 = pack2(hv.y);
                    fma2(a00, h0, rv.x); fma2(a01, h0, rv.y);
                    fma2(a10, h1, rv.x); fma2(a11, h1, rv.y);
                }
                if (c == 3) break;
                __syncthreads();                  // readers done with Rb[c&1]
                if (c < 2) {
#pragma unroll
                    for (int ii = 0; ii < 4; ii++)
                        cpa16(&Rb[(c & 1) * 4096 + (tid + ii * 256) * 4],
                              Rglob + (size_t)(c + 2) * 4096 + (size_t)(tid + ii * 256) * 4);
                    cpa_commit();
                }
                if (c == 2) cpa_wait0(); else cpa_wait1();
                __syncthreads();
            }
        }

        // gates for 2 cells
        float z0, z1, z2, z3;
        unpack2(a00, z0, z1); unpack2(a01, z2, z3);
        z0 += xv0.x; z1 += xv0.y; z2 += xv0.z; z3 += xv0.w;
        float ig = sigm_(z0), fg = sigm_(z1), gg = tanh_(z2), og = sigm_(z3);
        float cn0 = fmaf(fg, cc0, ig * gg); cc0 = cn0;
        float hn0 = og * tanh_(cn0);
        unpack2(a10, z0, z1); unpack2(a11, z2, z3);
        z0 += xv1.x; z1 += xv1.y; z2 += xv1.z; z3 += xv1.w;
        ig = sigm_(z0); fg = sigm_(z1); gg = tanh_(z2); og = sigm_(z3);
        float cn1 = fmaf(fg, cc1, ig * gg); cc1 = cn1;
        float hn1 = og * tanh_(cn1);

        *(float2*)(g_hTL[layer][wr][dir] + (u0 + zg) * BB + brow) = make_float2(hn0, hn1);
        stage[(2 * bp2) * 16 + zg]     = hn0;
        stage[(2 * bp2 + 1) * 16 + zg] = hn1;
        __syncthreads();
        // sequence output BEFORE arrive (release publishes it to proj1 / group mates)
        if (tid < 128) {
            int b = tid >> 2, q = tid & 3;
            *(float4*)(outb + (size_t)(t * BB + b0 + b) * UU + u0 + q * 4) =
                *(const float4*)&stage[b * 16 + q * 4];
        }
        __syncthreads();

        if (tid == 0) {
            int old = atom_add_acqrel(&cnt[grp]);
            if (old == 15) { cnt[grp] = 0; st_release(&gen[grp], s + 1); }
        }
        if (s + 1 < TT) {
            int tn2 = dir ? (TT - 2 - s) : (s + 1);
            if (tid == 0) { while (ld_acquire(&pd[tn2]) < 16) { } }
            __syncthreads();
            xv0 = *(const float4*)(xzb + (size_t)(tn2 * BB + brow) * ZZ + zc0 + zg * 4);
            xv1 = *(const float4*)(xzb + (size_t)(tn2 * BB + brow + 1) * ZZ + zc0 + zg * 4);
        }
        if (tid == 0) { while (ld_acquire(&gen[grp]) != s + 1) { } }
        __syncthreads();
    }
}

// ---------------- proj body: persistent workers, ticketed 64x128x256 tiles ----------
// tile j: q = j>>5 (t-order), r = j&31: d = r>>4, nb = (r>>1)&7, mh = r&1.
__device__ __forceinline__ void proj_body(int layer, float* sm, const float* __restrict__ x) {
    float* As = sm;              // [2][16][64]
    float* Bs = sm + 2048;       // [2][16][128]
    int* sjp  = (int*)(sm + 8192);
    int tid = threadIdx.x;
    int tm = (tid >> 4) << 2;
    int tn = (tid & 15) << 3;
    int arow = tid >> 2, akq = (tid & 3) << 2;
    int brow = tid >> 4, bc = (tid & 15) << 3;
    int* tk = layer ? &g_tk1 : &g_tk0;

    for (;;) {
        if (tid == 0) *sjp = atomicAdd(tk, 1);
        __syncthreads();
        int j = *sjp;
        if (j >= NTILES) return;
        int q = j >> 5, r = j & 31;
        int d = r >> 4, nb = (r >> 1) & 7, mh = r & 1;
        int t = d ? (TT - 1 - q) : q;
        if (layer == 1) {
            if (tid == 0) {
                while (ld_acquire(&g_gen0[d * 4 + mh * 2])     < q + 1) { }
                while (ld_acquire(&g_gen0[d * 4 + mh * 2 + 1]) < q + 1) { }
            }
            __syncthreads();
        }
        const float* A; size_t astr;
        if (layer == 0) { A = x + (size_t)(mh * 64) * 65536 + (size_t)t * 256; astr = 65536; }
        else            { A = g_h0[d] + (size_t)(t * 128 + mh * 64) * 256;      astr = 256;  }
        const float* Bp  = g_Wp[layer][d] + (size_t)brow * ZZ + nb * 128 + bc;
        const float* bpv = g_bp[layer][d] + nb * 128;
        float* C = (layer ? g_xz1 : g_xz0)[d] + (size_t)(t * 128 + mh * 64) * ZZ + nb * 128;

        unsigned long long acc2[4][4];
#pragma unroll
        for (int i = 0; i < 4; i++)
#pragma unroll
            for (int jj = 0; jj < 4; jj++) acc2[i][jj] = 0ULL;

        const float* Ap = A + (size_t)arow * astr + akq;
        {
            float4 av = *(const float4*)Ap;
            As[(akq + 0) * 64 + arow] = av.x;
            As[(akq + 1) * 64 + arow] = av.y;
            As[(akq + 2) * 64 + arow] = av.z;
            As[(akq + 3) * 64 + arow] = av.w;
        }
        cpa16(&Bs[brow * 128 + bc], Bp);
        cpa16(&Bs[brow * 128 + bc + 4], Bp + 4);
        cpa_commit();
        float4 avn = *(const float4*)(Ap + 16);

        for (int it = 0; it < 16; it++) {
            int cur = it & 1, nxt = cur ^ 1;
            cpa_wait0();
            __syncthreads();
            if (it < 15) {
                float* An = As + nxt * 1024;
                An[(akq + 0) * 64 + arow] = avn.x;
                An[(akq + 1) * 64 + arow] = avn.y;
                An[(akq + 2) * 64 + arow] = avn.z;
                An[(akq + 3) * 64 + arow] = avn.w;
                cpa16(&Bs[nxt * 2048 + brow * 128 + bc], Bp + (size_t)(it + 1) * 16 * ZZ);
                cpa16(&Bs[nxt * 2048 + brow * 128 + bc + 4], Bp + (size_t)(it + 1) * 16 * ZZ + 4);
                cpa_commit();
                if (it < 14) avn = *(const float4*)(Ap + (it + 2) * 16);
            }
            const float* Ac = As + cur * 1024;
            const float* Bc = Bs + cur * 2048;
#pragma unroll
            for (int kk = 0; kk < 16; kk++) {
                float4 a4 = *(const float4*)&Ac[kk * 64 + tm];
                ulonglong2 b01 = *(const ulonglong2*)&Bc[kk * 128 + tn];
                ulonglong2 b23 = *(const ulonglong2*)&Bc[kk * 128 + tn + 4];
                unsigned long long ad[4] = {pack2(a4.x), pack2(a4.y), pack2(a4.z), pack2(a4.w)};
#pragma unroll
                for (int i = 0; i < 4; i++) {
                    fma2(acc2[i][0], ad[i], b01.x);
                    fma2(acc2[i][1], ad[i], b01.y);
                    fma2(acc2[i][2], ad[i], b23.x);
                    fma2(acc2[i][3], ad[i], b23.y);
                }
            }
        }
        float bv[8];
#pragma unroll
        for (int jj = 0; jj < 8; jj++) bv[jj] = bpv[tn + jj];
#pragma unroll
        for (int i = 0; i < 4; i++) {
            float* cp = C + (size_t)(tm + i) * ZZ + tn;
            float c0, c1, c2, c3, c4, c5, c6, c7;
            unpack2(acc2[i][0], c0, c1);
            unpack2(acc2[i][1], c2, c3);
            unpack2(acc2[i][2], c4, c5);
            unpack2(acc2[i][3], c6, c7);
            float4 v0, v1;
            v0.x = c0 + bv[0]; v0.y = c1 + bv[1]; v0.z = c2 + bv[2]; v0.w = c3 + bv[3];
            v1.x = c4 + bv[4]; v1.y = c5 + bv[5]; v1.z = c6 + bv[6]; v1.w = c7 + bv[7];
            *(float4*)cp = v0;
            *(float4*)(cp + 4) = v1;
        }
        __syncthreads();   // C stores program-order before release add
        if (tid == 0) atom_add_acqrel(layer ? &g_pd1[d][t] : &g_pd0[d][t]);
    }
}

// ---------------- fused pipeline: 420 CTAs, 3/SM (capacity 444) ---------------------
__global__ __launch_bounds__(256, 3) void fused_kernel(const float* __restrict__ x) {
    extern __shared__ float sm[];
    int bid = blockIdx.x;
    if (bid < 128)          scan_body(0, bid, sm);
    else if (bid < 256)     scan_body(1, bid - 128, sm);
    else if (bid < 256 + NP) proj_body(0, sm, x);
    else                    proj_body(1, sm, x);
}

// ---------------- merge: out[b][t][u] = 0.5*(h1f + h0f + h1b + h0b) -----------------
__global__ void merge_kernel(float* __restrict__ out) {
    int i = blockIdx.x * blockDim.x + threadIdx.x;
    if (i >= TT * BB * UU / 4) return;
    int u4 = i & 63;
    int b  = (i >> 6) & 127;
    int t  = i >> 13;
    const float4 a = ((const float4*)g_h1[0])[i];
    const float4 c = ((const float4*)g_h0[0])[i];
    const float4 d = ((const float4*)g_h1[1])[i];
    const float4 e = ((const float4*)g_h0[1])[i];
    float4 r;
    r.x = 0.5f * (a.x + c.x + d.x + e.x);
    r.y = 0.5f * (a.y + c.y + d.y + e.y);
    r.z = 0.5f * (a.z + c.z + d.z + e.z);
    r.w = 0.5f * (a.w + c.w + d.w + e.w);
    ((float4*)out)[((b * TT + t) << 6) + u4] = r;
}

// ---------------- launch -------------------------------------------------------------
extern "C" void kernel_launch(void* const* d_in, const int* in_sizes, int n_in,
                              void* d_out, int out_size) {
    const float* x   = (const float*)d_in[0];
    const float* kfw = (const float*)d_in[1];
    const float* rfw = (const float*)d_in[2];
    const float* bfw = (const float*)d_in[3];
    const float* kbw = (const float*)d_in[4];
    const float* rbw = (const float*)d_in[5];
    const float* bbw = (const float*)d_in[6];
    float* out = (float*)d_out;

    // hs 32K + Rb 32K + stage 2K = 67584 bytes -> 3 CTAs/SM (202.8K of ~228K)
    const int fused_smem = 16896 * (int)sizeof(float);
    cudaFuncSetAttribute(fused_kernel, cudaFuncAttributeMaxDynamicSharedMemorySize, fused_smem);

    prep_kernel<<<4096, 256>>>(kfw, rfw, bfw, kbw, rbw, bbw);
    zero_bar_kernel<<<1, 512>>>();
    fused_kernel<<<256 + 2 * NP, 256, fused_smem>>>(x);
    merge_kernel<<<8192, 256>>>(out);
}

// round 14
// speedup vs baseline: 1.0336x; 1.0336x over previous
#include <cuda_runtime.h>

#define BB 128
#define TT 256
#define DD 256
#define UU 256
#define ZZ 1024   // 4*U
#define NFUSED 256

// ---------------- scratch (device globals; no allocation allowed) ----------------
__device__ float g_xz0[2][TT * BB * ZZ];      // layer-0 gate inputs [dir][t][b][u*4+g]
__device__ float g_xz1[2][TT * BB * ZZ];      // layer-1 gate inputs (folded proj output)
__device__ float g_h0[2][TT * BB * UU];       // layer-0 outputs [dir][t][b][u]
__device__ float g_h1[2][TT * BB * UU];       // layer-1 raw lstm outputs
__device__ float g_hTL[2][2][2][UU * BB];     // [layer][buf][dir][u][b]
__device__ float g_Wp[2][2][DD * ZZ];         // [layer][dir][k][u*4+g]
__device__ float g_Rp[2][2][UU * ZZ];         // [layer][dir][k][u*4+g]
__device__ float g_bp[2][2][ZZ];
__device__ int g_cnt0[8], g_gen0[8];          // scan0 barriers (dir x bq); also proj1 progress
__device__ int g_cnt1[8], g_gen1[8];          // scan1 barriers

// ---------------- packed f32x2 helpers ---------------------------------------------
__device__ __forceinline__ void fma2(unsigned long long& d, unsigned long long a,
                                     unsigned long long b) {
    asm("fma.rn.f32x2 %0, %1, %2, %0;" : "+l"(d) : "l"(a), "l"(b));
}
__device__ __forceinline__ void add2(unsigned long long& d, unsigned long long a) {
    asm("add.rn.f32x2 %0, %0, %1;" : "+l"(d) : "l"(a));
}
__device__ __forceinline__ unsigned long long pack2(float x) {
    unsigned long long d; unsigned int u = __float_as_uint(x);
    asm("mov.b64 %0, {%1, %1};" : "=l"(d) : "r"(u));
    return d;
}
__device__ __forceinline__ void unpack2(unsigned long long v, float& lo, float& hi) {
    unsigned int a, b;
    asm("mov.b64 {%0, %1}, %2;" : "=r"(a), "=r"(b) : "l"(v));
    lo = __uint_as_float(a); hi = __uint_as_float(b);
}

// ---------------- acquire/release primitives ----------------------------------------
__device__ __forceinline__ int atom_add_acqrel(int* p) {
    int old;
    asm volatile("atom.acq_rel.gpu.global.add.s32 %0, [%1], 1;"
                 : "=r"(old) : "l"(p) : "memory");
    return old;
}
__device__ __forceinline__ void st_release(int* p, int v) {
    asm volatile("st.release.gpu.global.s32 [%0], %1;" :: "l"(p), "r"(v) : "memory");
}
__device__ __forceinline__ int ld_acquire(int* p) {
    int v;
    asm volatile("ld.acquire.gpu.global.s32 %0, [%1];" : "=r"(v) : "l"(p) : "memory");
    return v;
}

// ---------------- cp.async helpers --------------------------------------------------
__device__ __forceinline__ void cpa16(void* smem, const void* g) {
    unsigned s = (unsigned)__cvta_generic_to_shared(smem);
    asm volatile("cp.async.cg.shared.global [%0], [%1], 16;" :: "r"(s), "l"(g));
}
__device__ __forceinline__ void cpa_commit() { asm volatile("cp.async.commit_group;"); }
__device__ __forceinline__ void cpa_wait0()  { asm volatile("cp.async.wait_group 0;"); }

// ---------------- MUFU-free fast math ----------------------------------------------
__device__ __forceinline__ float fast_exp(float x) {
    x = fminf(fmaxf(x, -80.0f), 80.0f);
    float y = x * 1.442695041f;
    float t = y + 12582912.0f;
    float n = t - 12582912.0f;
    float f = y - n;
    int   ni = __float_as_int(t) - 0x4B400000;
    float p = 1.54035304e-4f;
    p = fmaf(p, f, 1.33335581e-3f);
    p = fmaf(p, f, 9.61812910e-3f);
    p = fmaf(p, f, 5.55041087e-2f);
    p = fmaf(p, f, 2.40226507e-1f);
    p = fmaf(p, f, 6.93147182e-1f);
    p = fmaf(p, f, 1.0f);
    return p * __int_as_float((ni + 127) << 23);
}
__device__ __forceinline__ float fast_rcp(float a) {
    float r = __int_as_float(0x7EF311C3 - __float_as_int(a));
    r = r * fmaf(-a, r, 2.0f);
    r = r * fmaf(-a, r, 2.0f);
    r = r * fmaf(-a, r, 2.0f);
    return r;
}
__device__ __forceinline__ float sigm_(float x) { return fast_rcp(1.0f + fast_exp(-x)); }
__device__ __forceinline__ float tanh_(float x) { return fmaf(-2.0f, fast_rcp(1.0f + fast_exp(2.0f * x)), 1.0f); }

// ---------------- weight permutation -------------------------------------------------
__global__ void prep_kernel(const float* __restrict__ kfw, const float* __restrict__ rfw,
                            const float* __restrict__ bfw, const float* __restrict__ kbw,
                            const float* __restrict__ rbw, const float* __restrict__ bbw) {
    int idx = blockIdx.x * blockDim.x + threadIdx.x;
    if (idx >= 2 * 2 * DD * ZZ) return;
    int e  = idx & (DD * ZZ - 1);
    int ld = idx >> 18;
    int l = ld >> 1, d = ld & 1;
    int k  = e >> 10;
    int uu = e & 1023;
    int u = uu >> 2, g = uu & 3;
    int src_col = g * UU + u;
    const float* Ksrc = d ? kbw : kfw;
    const float* Rsrc = d ? rbw : rfw;
    g_Wp[l][d][e] = Ksrc[l * DD * ZZ + k * ZZ + src_col];
    g_Rp[l][d][e] = Rsrc[l * UU * ZZ + k * ZZ + src_col];
    if (k == 0) {
        const float* bsrc = d ? bbw : bfw;
        g_bp[l][d][uu] = bsrc[l * ZZ + src_col];
    }
}

__global__ void zero_bar_kernel() {
    int i = threadIdx.x;
    if (i < 8) { g_cnt0[i] = 0; g_gen0[i] = 0; g_cnt1[i] = 0; g_gen1[i] = 0; }
}

// ---------------- layer-0 input projection (serial, R10-validated) ------------------
__global__ __launch_bounds__(256, 2) void proj_kernel(const float* __restrict__ x) {
    int dir = blockIdx.z;
    const float* A  = x;
    const float* Wp = g_Wp[0][dir];
    const float* bp = g_bp[0][dir];
    float* C = g_xz0[dir];
    const int m0 = blockIdx.y * 128;
    const int n0 = blockIdx.x * 128;
    __shared__ float As[2][16][128];
    __shared__ float Bs[2][16][128];
    int tid = threadIdx.x;
    int tm = (tid >> 4) << 3;
    int tn = (tid & 15) << 3;
    unsigned long long acc2[8][4];
#pragma unroll
    for (int i = 0; i < 8; i++)
#pragma unroll
        for (int j = 0; j < 4; j++) acc2[i][j] = 0ULL;

    int arow = tid >> 1, akq = (tid & 1) << 3;
    int brow = tid >> 4, bc = (tid & 15) << 3;
    const float* Ap = A + (size_t)(m0 + arow) * DD + akq;
    const float* Bp = Wp + (size_t)brow * ZZ + n0 + bc;

    {
        float4 a0 = *(const float4*)Ap;
        float4 a1 = *(const float4*)(Ap + 4);
        As[0][akq + 0][arow] = a0.x; As[0][akq + 1][arow] = a0.y;
        As[0][akq + 2][arow] = a0.z; As[0][akq + 3][arow] = a0.w;
        As[0][akq + 4][arow] = a1.x; As[0][akq + 5][arow] = a1.y;
        As[0][akq + 6][arow] = a1.z; As[0][akq + 7][arow] = a1.w;
    }
    cpa16(&Bs[0][brow][bc], Bp);
    cpa16(&Bs[0][brow][bc + 4], Bp + 4);
    cpa_commit();
    float4 av0 = *(const float4*)(Ap + 16);
    float4 av1 = *(const float4*)(Ap + 20);

    for (int it = 0; it < 16; it++) {
        int cur = it & 1, nxt = cur ^ 1;
        cpa_wait0();
        __syncthreads();
        if (it < 15) {
            As[nxt][akq + 0][arow] = av0.x; As[nxt][akq + 1][arow] = av0.y;
            As[nxt][akq + 2][arow] = av0.z; As[nxt][akq + 3][arow] = av0.w;
            As[nxt][akq + 4][arow] = av1.x; As[nxt][akq + 5][arow] = av1.y;
            As[nxt][akq + 6][arow] = av1.z; As[nxt][akq + 7][arow] = av1.w;
            cpa16(&Bs[nxt][brow][bc], Bp + (size_t)(it + 1) * 16 * ZZ);
            cpa16(&Bs[nxt][brow][bc + 4], Bp + (size_t)(it + 1) * 16 * ZZ + 4);
            cpa_commit();
            if (it < 14) {
                av0 = *(const float4*)(Ap + (it + 2) * 16);
                av1 = *(const float4*)(Ap + (it + 2) * 16 + 4);
            }
        }
#pragma unroll
        for (int kk = 0; kk < 16; kk++) {
            float a[8];
            *(float4*)&a[0] = *(float4*)&As[cur][kk][tm];
            *(float4*)&a[4] = *(float4*)&As[cur][kk][tm + 4];
            ulonglong2 b01 = *(const ulonglong2*)&Bs[cur][kk][tn];
            ulonglong2 b23 = *(const ulonglong2*)&Bs[cur][kk][tn + 4];
#pragma unroll
            for (int i = 0; i < 8; i++) {
                unsigned long long ai = pack2(a[i]);
                fma2(acc2[i][0], ai, b01.x);
                fma2(acc2[i][1], ai, b01.y);
                fma2(acc2[i][2], ai, b23.x);
                fma2(acc2[i][3], ai, b23.y);
            }
        }
    }
    float bv[8];
#pragma unroll
    for (int j = 0; j < 8; j++) bv[j] = bp[n0 + tn + j];
#pragma unroll
    for (int i = 0; i < 8; i++) {
        int m = m0 + tm + i;
        int crow = (m & 255) * BB + (m >> 8);   // A row b*256+t -> C row t*128+b
        float* cp = C + (size_t)crow * ZZ + n0 + tn;
        float c0, c1, c2, c3, c4, c5, c6, c7;
        unpack2(acc2[i][0], c0, c1);
        unpack2(acc2[i][1], c2, c3);
        unpack2(acc2[i][2], c4, c5);
        unpack2(acc2[i][3], c6, c7);
        float4 v0, v1;
        v0.x = c0 + bv[0]; v0.y = c1 + bv[1]; v0.z = c2 + bv[2]; v0.w = c3 + bv[3];
        v1.x = c4 + bv[4]; v1.y = c5 + bv[5]; v1.z = c6 + bv[6]; v1.w = c7 + bv[7];
        *(float4*)cp = v0;
        *(float4*)(cp + 4) = v1;
    }
}

// ---------------- folded proj1 tile: 32b x 64n x 256k ------------------------------
// A = h0[dir][t(q)][b0..b0+32][:] (32KB contiguous), staged into hs.
// Cols = the CTA's own z-slice zc0..+64. Writes xz1. Caller syncs + arrives after.
__device__ __forceinline__ void proj1_tile(int dir, int q, int b0, int zc0,
                                           float* hs, float4 bv, int tidb, int tidn) {
    int t = dir ? (TT - 1 - q) : q;
    {
        const float4* src = (const float4*)(g_h0[dir] + (size_t)(t * BB + b0) * UU);
        float4* dst = (float4*)hs;
        int tid = threadIdx.x;
#pragma unroll
        for (int r = 0; r < 8; r++) cpa16(&dst[tid + r * 256], src + tid + r * 256);
        cpa_commit();
        cpa_wait0();
    }
    __syncthreads();
    const float* A0 = hs + (2 * tidb) * 256;
    const float* A1 = A0 + 256;
    const float* Wp = g_Wp[1][dir] + zc0 + tidn * 4;
    unsigned long long a00 = 0, a01 = 0, a10 = 0, a11 = 0;
#pragma unroll 2
    for (int kq = 0; kq < 64; kq++) {
        float4 av0 = *(const float4*)(A0 + kq * 4);
        float4 av1 = *(const float4*)(A1 + kq * 4);
        ulonglong2 w0 = *(const ulonglong2*)(Wp + (size_t)(kq * 4 + 0) * ZZ);
        ulonglong2 w1 = *(const ulonglong2*)(Wp + (size_t)(kq * 4 + 1) * ZZ);
        ulonglong2 w2 = *(const ulonglong2*)(Wp + (size_t)(kq * 4 + 2) * ZZ);
        ulonglong2 w3 = *(const ulonglong2*)(Wp + (size_t)(kq * 4 + 3) * ZZ);
        unsigned long long p0, p1;
        p0 = pack2(av0.x); p1 = pack2(av1.x);
        fma2(a00, p0, w0.x); fma2(a01, p0, w0.y);
        fma2(a10, p1, w0.x); fma2(a11, p1, w0.y);
        p0 = pack2(av0.y); p1 = pack2(av1.y);
        fma2(a00, p0, w1.x); fma2(a01, p0, w1.y);
        fma2(a10, p1, w1.x); fma2(a11, p1, w1.y);
        p0 = pack2(av0.z); p1 = pack2(av1.z);
        fma2(a00, p0, w2.x); fma2(a01, p0, w2.y);
        fma2(a10, p1, w2.x); fma2(a11, p1, w2.y);
        p0 = pack2(av0.w); p1 = pack2(av1.w);
        fma2(a00, p0, w3.x); fma2(a01, p0, w3.y);
        fma2(a10, p1, w3.x); fma2(a11, p1, w3.y);
    }
    float z0, z1, z2, z3;
    float* C = g_xz1[dir] + (size_t)(t * BB + b0 + 2 * tidb) * ZZ + zc0 + tidn * 4;
    unpack2(a00, z0, z1); unpack2(a01, z2, z3);
    *(float4*)C = make_float4(z0 + bv.x, z1 + bv.y, z2 + bv.z, z3 + bv.w);
    unpack2(a10, z0, z1); unpack2(a11, z2, z3);
    *(float4*)(C + ZZ) = make_float4(z0 + bv.x, z1 + bv.y, z2 + bv.z, z3 + bv.w);
}

// ---------------- scan body (layer 0 folds proj1; layer 1 gates on gen0) ------------
// 128 CTAs per layer, groups of 16 sharing (dir,bq). R resident; c in registers.
__device__ __forceinline__ void scan_body(int layer, int sub, float* sm) {
    float* Rs = sm;                                   // 64 KB
    float* hs = sm + UU * 64;                         // 32 KB (h tile; proj A staging)
    unsigned long long* red = (unsigned long long*)(hs + UU * 32);  // 8 KB
    float* stage = (float*)(red + 256 * 4);           // 2 KB

    int dir  = sub >> 6;
    int rest = sub & 63;
    int b0  = (rest >> 4) * 32;
    int zi  = rest & 15;
    int zc0 = zi * 64;
    int u0  = zi * 16;
    int grp = sub >> 4;                // dir*4 + bq
    int tid = threadIdx.x;
    int kh   = tid >> 7;
    int wtid = tid & 127;
    int zg  = wtid & 15;
    int bgr = wtid >> 4;
    int bb  = b0 + bgr * 4 + kh * 2;
    int tidb = tid >> 4, tidn = tid & 15;   // proj roles

    int* cnt = layer ? g_cnt1 : g_cnt0;
    int* gen = layer ? g_gen1 : g_gen0;
    const float* xzb = (layer ? g_xz1 : g_xz0)[dir];
    float* outb = (layer ? g_h1 : g_h0)[dir];

    float4 bv1 = make_float4(0.f, 0.f, 0.f, 0.f);
    if (layer == 0)
        bv1 = *(const float4*)(g_bp[1][dir] + zc0 + tidn * 4);

    // load R slice once
    {
        const float* Rp = g_Rp[layer][dir];
        float4* Rs4 = (float4*)Rs;
        for (int idx = tid; idx < 4096; idx += 256) {
            int k = idx >> 4, c = idx & 15;
            Rs4[idx] = *(const float4*)(Rp + k * ZZ + zc0 + c * 4);
        }
    }
    float cc[2] = {0.0f, 0.0f};

    // step-0 xz (layer1 gates on scan0/proj progress: gen0 >= 2)
    int t0 = dir ? (TT - 1) : 0;
    if (layer) {
        if (tid == 0) { while (ld_acquire(&g_gen0[grp]) < 2) { } }
        __syncthreads();
    }
    float4 xv[2];
    {
        const float* xp = xzb + (size_t)(t0 * BB + bb) * ZZ + zc0 + zg * 4;
        xv[0] = *(const float4*)(xp);
        xv[1] = *(const float4*)(xp + ZZ);
    }
    __syncthreads();

    for (int s = 0; s < TT; s++) {
        int t  = dir ? (TT - 1 - s) : s;
        int rd = s & 1, wr = rd ^ 1;

        // fill h tile [256 k][32 b]
        float4* hs4 = (float4*)hs;
        if (s == 0) {
            for (int idx = tid; idx < 2048; idx += 256)
                hs4[idx] = make_float4(0.f, 0.f, 0.f, 0.f);
        } else {
            const float4* src = (const float4*)(g_hTL[layer][rd][dir]);
            for (int idx = tid; idx < 2048; idx += 256) {
                int k = idx >> 3, q = idx & 7;
                cpa16(&hs4[idx], src + k * 32 + (b0 >> 2) + q);
            }
            cpa_commit();
            cpa_wait0();
        }
        __syncthreads();

        // GEMM half: acc(4b x 4zc) over 128 k
        unsigned long long acc[8];
#pragma unroll
        for (int j = 0; j < 8; j++) acc[j] = 0ULL;
        {
            const float* hrow = hs + kh * 128 * 32 + bgr * 4;
            const float* rrow = Rs + kh * 128 * 64 + zg * 4;
#pragma unroll 4
            for (int k = 0; k < 128; k++) {
                float4 hv = *(const float4*)(hrow + k * 32);
                ulonglong2 rv = *(const ulonglong2*)(rrow + k * 64);
                unsigned long long h0 = pack2(hv.x), h1 = pack2(hv.y);
                unsigned long long h2 = pack2(hv.z), h3 = pack2(hv.w);
                fma2(acc[0], h0, rv.x); fma2(acc[1], h0, rv.y);
                fma2(acc[2], h1, rv.x); fma2(acc[3], h1, rv.y);
                fma2(acc[4], h2, rv.x); fma2(acc[5], h2, rv.y);
                fma2(acc[6], h3, rv.x); fma2(acc[7], h3, rv.y);
            }
        }
        {
            int oh = (kh ^ 1) * 4;
#pragma unroll
            for (int j = 0; j < 4; j++) red[tid * 4 + j] = acc[oh + j];
        }
        __syncthreads();
        // finalize 2 cells
        {
            const unsigned long long* pr = &red[(tid ^ 128) * 4];
            float hn[2];
#pragma unroll
            for (int ii = 0; ii < 2; ii++) {
                int i = kh * 2 + ii;
                unsigned long long z01 = acc[i * 2 + 0];
                unsigned long long z23 = acc[i * 2 + 1];
                add2(z01, pr[ii * 2 + 0]);
                add2(z23, pr[ii * 2 + 1]);
                float z0, z1, z2, z3;
                unpack2(z01, z0, z1);
                unpack2(z23, z2, z3);
                z0 += xv[ii].x; z1 += xv[ii].y; z2 += xv[ii].z; z3 += xv[ii].w;
                float ig = sigm_(z0);
                float fg = sigm_(z1);
                float gg = tanh_(z2);
                float og = sigm_(z3);
                float cn = fmaf(fg, cc[ii], ig * gg);
                cc[ii] = cn;
                hn[ii] = og * tanh_(cn);
            }
            int u = u0 + zg;
            *(float2*)(g_hTL[layer][wr][dir] + u * BB + bb) = make_float2(hn[0], hn[1]);
            stage[(bgr * 4 + kh * 2 + 0) * 16 + zg] = hn[0];
            stage[(bgr * 4 + kh * 2 + 1) * 16 + zg] = hn[1];
        }
        __syncthreads();
        // sequence output BEFORE arrive (release publishes h0[t] to the group/proj)
        if (tid < 128) {
            int row = tid >> 2, q = tid & 3;
            *(float4*)(outb + (size_t)(t * BB + b0 + row) * UU + u0 + q * 4) =
                ((float4*)stage)[tid];
        }
        __syncthreads();

        // ---- layer0: folded proj1 tile for q = s-1 (h0 visible via own group) ----
        if (layer == 0 && s >= 1) {
            proj1_tile(dir, s - 1, b0, zc0, hs, bv1, tidb, tidn);
            __syncthreads();   // xz1 stores program-order before the release arrive
        }

        // group barrier (acq/rel): arrive, hide xz prefetch, wait
        if (tid == 0) {
            int old = atom_add_acqrel(&cnt[grp]);
            if (old == 15) { cnt[grp] = 0; st_release(&gen[grp], s + 1); }
        }
        if (s + 1 < TT) {
            int tn2 = dir ? (TT - 2 - s) : (s + 1);
            if (layer) {
                if (tid == 0) { while (ld_acquire(&g_gen0[grp]) < s + 3) { } }
                __syncthreads();
            }
            const float* xp = xzb + (size_t)(tn2 * BB + bb) * ZZ + zc0 + zg * 4;
            xv[0] = *(const float4*)(xp);
            xv[1] = *(const float4*)(xp + ZZ);
        }
        if (tid == 0) {
            while (ld_acquire(&gen[grp]) != s + 1) { }
        }
        __syncthreads();
    }

    // layer0 epilogue: final proj1 tile (q = TT-1), then release gen0 = TT+1
    if (layer == 0) {
        proj1_tile(dir, TT - 1, b0, zc0, hs, bv1, tidb, tidn);
        __syncthreads();
        if (tid == 0) {
            int old = atom_add_acqrel(&cnt[grp]);
            if (old == 15) { cnt[grp] = 0; st_release(&gen[grp], TT + 1); }
        }
    }
}

// ---------------- fused: 256 CTAs, 2/SM, scan0(+proj1) || scan1 ---------------------
__global__ __launch_bounds__(256, 2) void fused_kernel() {
    extern __shared__ float sm[];
    int bid = blockIdx.x;
    if (bid < 128) scan_body(0, bid, sm);
    else           scan_body(1, bid - 128, sm);
}

// ---------------- merge: out[b][t][u] = 0.5*(h1f + h0f + h1b + h0b) -----------------
__global__ void merge_kernel(float* __restrict__ out) {
    int i = blockIdx.x * blockDim.x + threadIdx.x;
    if (i >= TT * BB * UU / 4) return;
    int u4 = i & 63;
    int b  = (i >> 6) & 127;
    int t  = i >> 13;
    const float4 a = ((const float4*)g_h1[0])[i];
    const float4 c = ((const float4*)g_h0[0])[i];
    const float4 d = ((const float4*)g_h1[1])[i];
    const float4 e = ((const float4*)g_h0[1])[i];
    float4 r;
    r.x = 0.5f * (a.x + c.x + d.x + e.x);
    r.y = 0.5f * (a.y + c.y + d.y + e.y);
    r.z = 0.5f * (a.z + c.z + d.z + e.z);
    r.w = 0.5f * (a.w + c.w + d.w + e.w);
    ((float4*)out)[((b * TT + t) << 6) + u4] = r;
}

// ---------------- launch -------------------------------------------------------------
extern "C" void kernel_launch(void* const* d_in, const int* in_sizes, int n_in,
                              void* d_out, int out_size) {
    const float* x   = (const float*)d_in[0];
    const float* kfw = (const float*)d_in[1];
    const float* rfw = (const float*)d_in[2];
    const float* bfw = (const float*)d_in[3];
    const float* kbw = (const float*)d_in[4];
    const float* rbw = (const float*)d_in[5];
    const float* bbw = (const float*)d_in[6];
    float* out = (float*)d_out;

    // Rs 64K + hs 32K + red 8K + stage 2K = 108544 bytes -> 2 CTAs/SM
    const int fused_smem = (UU * 64 + UU * 32) * 4 + 256 * 4 * 8 + 2048;
    cudaFuncSetAttribute(fused_kernel, cudaFuncAttributeMaxDynamicSharedMemorySize, fused_smem);

    prep_kernel<<<4096, 256>>>(kfw, rfw, bfw, kbw, rbw, bbw);
    zero_bar_kernel<<<1, 32>>>();
    proj_kernel<<<dim3(8, 256, 2), 256>>>(x);
    fused_kernel<<<NFUSED, 256, fused_smem>>>();
    merge_kernel<<<8192, 256>>>(out);
}